// round 4
// baseline (speedup 1.0000x reference)
#include <cuda_runtime.h>
#include <math.h>

#define NL   3
#define NB   64
#define NSEQ 48
#define DM   256
#define NH   8
#define HDM  32
#define FFD  1024
#define INP  17
#define NTH  512

// ---------------- static device scratch (no runtime allocation) ----------------
__device__ float g_wqT[NL][DM][DM];     // wqT[l][j][r] = w_qkv[l][r][j],      r in [0,256)
__device__ float g_wkT[NL][DM][DM];     //                                    r in [256,512)
__device__ float g_wvT[NL][DM][DM];     //                                    r in [512,768)
__device__ float g_woT[NL][DM][DM];     // woT[l][j][r] = w_o[l][r][j]
__device__ float g_wff1T[NL][DM][FFD];  // [j][r]
__device__ float g_wff2T[NL][FFD][DM];  // [j][r]
__device__ float g_winT[INP][DM];
__device__ float g_wp1T[DM][128];
__device__ float g_kc[NL][NB][NSEQ][DM];
__device__ float g_vc[NL][NB][NSEQ][DM];

// ---------------- prep: transpose weights for coalesced GEMV loads ----------------
__global__ void prep_kernel(const float* __restrict__ w_qkv, const float* __restrict__ w_o,
                            const float* __restrict__ w_ff1, const float* __restrict__ w_ff2,
                            const float* __restrict__ w_in,  const float* __restrict__ w_p1)
{
    int tid = blockIdx.x * blockDim.x + threadIdx.x;
    int nth = gridDim.x * blockDim.x;

    for (int i = tid; i < NL*3*DM*DM; i += nth) {
        int l = i / (3*DM*DM); int rem = i - l*3*DM*DM; int r = rem / DM; int j = rem - r*DM;
        float v = w_qkv[i];
        int sel = r >> 8; int rr = r & 255;
        if (sel == 0)      g_wqT[l][j][rr] = v;
        else if (sel == 1) g_wkT[l][j][rr] = v;
        else               g_wvT[l][j][rr] = v;
    }
    for (int i = tid; i < NL*DM*DM; i += nth) {
        int l = i / (DM*DM); int rem = i - l*DM*DM; int r = rem / DM; int j = rem - r*DM;
        g_woT[l][j][r] = w_o[i];
    }
    for (int i = tid; i < NL*FFD*DM; i += nth) {
        int l = i / (FFD*DM); int rem = i - l*FFD*DM; int r = rem / DM; int j = rem - r*DM;
        g_wff1T[l][j][r] = w_ff1[i];
    }
    for (int i = tid; i < NL*DM*FFD; i += nth) {
        int l = i / (DM*FFD); int rem = i - l*DM*FFD; int r = rem / FFD; int j = rem - r*FFD;
        g_wff2T[l][j][r] = w_ff2[i];
    }
    for (int i = tid; i < DM*INP; i += nth) {
        int r = i / INP; int j = i - r*INP;
        g_winT[j][r] = w_in[i];
    }
    for (int i = tid; i < 128*DM; i += nth) {
        int r = i / DM; int j = i - r*DM;
        g_wp1T[j][r] = w_p1[i];
    }
}

// ---------------- dual-RHS GEMV: each weight float4 feeds BOTH batch elements.
// 512 threads: thread owns 4 consecutive rows (group g), j-split s across threads.
// Partials: elem0 at part[0..2048), elem1 at part[2048..4096). S*O == 2048 always. ----
template<int O, int I>
__device__ __forceinline__ void gemv2(const float* __restrict__ wT,
                                      const float* __restrict__ x0,
                                      const float* __restrict__ x1,
                                      float* __restrict__ part, int t)
{
    constexpr int G  = O / 4;        // float4 row-groups
    constexpr int S  = NTH / G;      // j-splits
    constexpr int JC = I / S;        // j-range per split (multiple of 4)
    const int g = t % G;
    const int s = t / G;
    const float4* __restrict__ w4  = reinterpret_cast<const float4*>(wT);
    const float4* __restrict__ xa4 = reinterpret_cast<const float4*>(x0);
    const float4* __restrict__ xb4 = reinterpret_cast<const float4*>(x1);
    float ax=0.f, ay=0.f, az=0.f, aw=0.f;
    float bx=0.f, by=0.f, bz=0.f, bw=0.f;
    const int jb = s * JC;
    #pragma unroll 2
    for (int u = 0; u < JC/4; ++u) {
        float4 av = xa4[(jb >> 2) + u];
        float4 bv = xb4[(jb >> 2) + u];
        const float4* wp = w4 + (size_t)(jb + 4*u) * G + g;
        float4 w0 = wp[0];
        float4 w1 = wp[G];
        float4 w2 = wp[2*G];
        float4 w3 = wp[3*G];
        ax=fmaf(w0.x,av.x,ax); ay=fmaf(w0.y,av.x,ay); az=fmaf(w0.z,av.x,az); aw=fmaf(w0.w,av.x,aw);
        bx=fmaf(w0.x,bv.x,bx); by=fmaf(w0.y,bv.x,by); bz=fmaf(w0.z,bv.x,bz); bw=fmaf(w0.w,bv.x,bw);
        ax=fmaf(w1.x,av.y,ax); ay=fmaf(w1.y,av.y,ay); az=fmaf(w1.z,av.y,az); aw=fmaf(w1.w,av.y,aw);
        bx=fmaf(w1.x,bv.y,bx); by=fmaf(w1.y,bv.y,by); bz=fmaf(w1.z,bv.y,bz); bw=fmaf(w1.w,bv.y,bw);
        ax=fmaf(w2.x,av.z,ax); ay=fmaf(w2.y,av.z,ay); az=fmaf(w2.z,av.z,az); aw=fmaf(w2.w,av.z,aw);
        bx=fmaf(w2.x,bv.z,bx); by=fmaf(w2.y,bv.z,by); bz=fmaf(w2.z,bv.z,bz); bw=fmaf(w2.w,bv.z,bw);
        ax=fmaf(w3.x,av.w,ax); ay=fmaf(w3.y,av.w,ay); az=fmaf(w3.z,av.w,az); aw=fmaf(w3.w,av.w,aw);
        bx=fmaf(w3.x,bv.w,bx); by=fmaf(w3.y,bv.w,by); bz=fmaf(w3.z,bv.w,bz); bw=fmaf(w3.w,bv.w,bw);
    }
    float4 A; A.x=ax; A.y=ay; A.z=az; A.w=aw;
    float4 B; B.x=bx; B.y=by; B.z=bz; B.w=bw;
    reinterpret_cast<float4*>(part)[s*G + g]       = A;
    reinterpret_cast<float4*>(part)[512 + s*G + g] = B;
}

__device__ __forceinline__ float gelu_exact(float x) {
    return 0.5f * x * (1.0f + erff(x * 0.70710678118654746f));
}

// dual-element block reduction: warps 0-7 hold element-0 values, 8-15 element-1.
__device__ __forceinline__ void block_reduce2_dual(float& a, float& b, float* red, int lane, int warp)
{
    #pragma unroll
    for (int m = 16; m; m >>= 1) {
        a += __shfl_xor_sync(0xffffffffu, a, m);
        b += __shfl_xor_sync(0xffffffffu, b, m);
    }
    if (lane == 0) { red[warp] = a; red[32 + warp] = b; }
    __syncthreads();
    if (warp < 2) {
        float aa = (lane < 8) ? red[warp*8 + lane]      : 0.f;
        float bb = (lane < 8) ? red[32 + warp*8 + lane] : 0.f;
        #pragma unroll
        for (int m = 4; m; m >>= 1) {
            aa += __shfl_xor_sync(0xffffffffu, aa, m);
            bb += __shfl_xor_sync(0xffffffffu, bb, m);
        }
        if (lane == 0) { red[48 + warp] = aa; red[52 + warp] = bb; }
    }
    __syncthreads();
    int e = warp >> 3;
    a = red[48 + e];
    b = red[52 + e];
}

// ---------------- main: one block per 2 batch elements, full autoregressive loop ----------------
__global__ __launch_bounds__(NTH, 1) void hedge_kernel(
    const float* __restrict__ feat,
    const float* __restrict__ b_in,
    const float* __restrict__ b_qkv,
    const float* __restrict__ b_o,
    const float* __restrict__ ln1_g, const float* __restrict__ ln1_b,
    const float* __restrict__ b_ff1, const float* __restrict__ b_ff2,
    const float* __restrict__ ln2_g, const float* __restrict__ ln2_b,
    const float* __restrict__ b_p1,
    const float* __restrict__ w_p2,  const float* __restrict__ b_p2,
    float* __restrict__ out)
{
    const int b0   = blockIdx.x * 2;
    const int t    = threadIdx.x;
    const int lane = t & 31;
    const int warp = t >> 5;

    __shared__ __align__(16) float xs[2][DM];
    __shared__ __align__(16) float qs[2][DM];
    __shared__ __align__(16) float ctx[2][DM];
    __shared__ __align__(16) float ffs[2][FFD];
    __shared__ __align__(16) float part[4096];
    __shared__ float sc[2][NH][NSEQ];
    __shared__ float h1[2][128];
    __shared__ float xin[2][INP + 3];
    __shared__ float red[64];
    __shared__ float sdelta[2];

    const int e8 = t >> 8;          // element for DM-sized stages
    const int r8 = t & 255;

    // sinusoidal PE factor for this dim
    const float div_t = expf((float)(r8 & ~1) * (-9.210340371976184f / 256.f));
    const float scale = 0.17677669529663687f;  // 1/sqrt(32)

    if (t < 2) sdelta[t] = 0.f;
    __syncthreads();

    for (int k = 0; k < NSEQ; ++k) {
        // ---- build token inputs [features(16), prev_delta] for both elements ----
        if (t < 16)       xin[0][t]      = feat[((b0*NSEQ)     + k)*16 + t];
        else if (t < 32)  xin[1][t - 16] = feat[(((b0+1)*NSEQ) + k)*16 + t - 16];
        else if (t == 32) xin[0][16] = sdelta[0];
        else if (t == 33) xin[1][16] = sdelta[1];
        __syncthreads();

        // ---- input projection + positional encoding ----
        {
            float acc = b_in[r8];
            #pragma unroll
            for (int j = 0; j < INP; ++j) acc = fmaf(g_winT[j][r8], xin[e8][j], acc);
            float ang = (float)k * div_t;
            acc += (r8 & 1) ? cosf(ang) : sinf(ang);
            xs[e8][r8] = acc;
        }
        __syncthreads();

        for (int l = 0; l < NL; ++l) {
            const float* bq = b_qkv + l*3*DM;

            // ---- Q ----
            gemv2<DM, DM>(&g_wqT[l][0][0], xs[0], xs[1], part, t);
            __syncthreads();
            {
                const float* p = part + e8*2048 + r8;
                qs[e8][r8] = p[0]+p[256]+p[512]+p[768]+p[1024]+p[1280]+p[1536]+p[1792] + bq[r8];
            }
            __syncthreads();
            // ---- K -> cache ----
            gemv2<DM, DM>(&g_wkT[l][0][0], xs[0], xs[1], part, t);
            __syncthreads();
            {
                const float* p = part + e8*2048 + r8;
                g_kc[l][b0+e8][k][r8] = p[0]+p[256]+p[512]+p[768]+p[1024]+p[1280]+p[1536]+p[1792] + bq[DM + r8];
            }
            __syncthreads();
            // ---- V -> cache ----
            gemv2<DM, DM>(&g_wvT[l][0][0], xs[0], xs[1], part, t);
            __syncthreads();
            {
                const float* p = part + e8*2048 + r8;
                g_vc[l][b0+e8][k][r8] = p[0]+p[256]+p[512]+p[768]+p[1024]+p[1280]+p[1536]+p[1792] + bq[2*DM + r8];
            }
            __syncthreads();

            // ---- attention: warp = (element e, head h); 32 lanes = 32 head dims ----
            {
                const int ea = warp >> 3;
                const int h  = warp & 7;
                const int off = h*HDM + lane;
                const float ql = qs[ea][off];
                const float* kcp = &g_kc[l][b0+ea][0][0];
                const float* vcp = &g_vc[l][b0+ea][0][0];
                float* scp = &sc[ea][h][0];
                int p = 0;
                for (; p + 1 <= k; p += 2) {
                    float s0 = ql * kcp[p*DM + off];
                    float s1 = ql * kcp[(p+1)*DM + off];
                    #pragma unroll
                    for (int m = 16; m; m >>= 1) {
                        s0 += __shfl_xor_sync(0xffffffffu, s0, m);
                        s1 += __shfl_xor_sync(0xffffffffu, s1, m);
                    }
                    if (lane == 0) { scp[p] = s0*scale; scp[p+1] = s1*scale; }
                }
                if (p <= k) {
                    float s0 = ql * kcp[p*DM + off];
                    #pragma unroll
                    for (int m = 16; m; m >>= 1) s0 += __shfl_xor_sync(0xffffffffu, s0, m);
                    if (lane == 0) scp[p] = s0*scale;
                }
                __syncwarp();
                float v0 = (lane      <= k) ? scp[lane]      : -3.0e38f;
                float v1 = (lane + 32 <= k) ? scp[lane + 32] : -3.0e38f;
                float mx = fmaxf(v0, v1);
                #pragma unroll
                for (int m = 16; m; m >>= 1) mx = fmaxf(mx, __shfl_xor_sync(0xffffffffu, mx, m));
                float e0 = (lane      <= k) ? expf(v0 - mx) : 0.f;
                float e1 = (lane + 32 <= k) ? expf(v1 - mx) : 0.f;
                float sum = e0 + e1;
                #pragma unroll
                for (int m = 16; m; m >>= 1) sum += __shfl_xor_sync(0xffffffffu, sum, m);
                float inv = 1.f / sum;
                if (lane      <= k) scp[lane]      = e0 * inv;
                if (lane + 32 <= k) scp[lane + 32] = e1 * inv;
                __syncwarp();
                float acc = 0.f;
                for (int pp = 0; pp <= k; ++pp)
                    acc = fmaf(scp[pp], vcp[pp*DM + off], acc);
                ctx[ea][off] = acc;
            }
            __syncthreads();

            // ---- O projection + residual + LN1 ----
            gemv2<DM, DM>(&g_woT[l][0][0], ctx[0], ctx[1], part, t);
            __syncthreads();
            {
                const float* p = part + e8*2048 + r8;
                float v = xs[e8][r8] + b_o[l*DM + r8]
                        + p[0]+p[256]+p[512]+p[768]+p[1024]+p[1280]+p[1536]+p[1792];
                float s1 = v, s2 = v*v;
                block_reduce2_dual(s1, s2, red, lane, warp);
                float m   = s1 * (1.f/256.f);
                float var = s2 * (1.f/256.f) - m*m;
                xs[e8][r8] = (v - m) * rsqrtf(var + 1e-5f) * ln1_g[l*DM + r8] + ln1_b[l*DM + r8];
            }
            __syncthreads();

            // ---- FF1 + exact GELU ----
            gemv2<FFD, DM>(&g_wff1T[l][0][0], xs[0], xs[1], part, t);
            __syncthreads();
            {
                const float* bf = b_ff1 + l*FFD;
                #pragma unroll
                for (int idx = t; idx < 2048; idx += NTH) {
                    int e = idx >> 10, r = idx & 1023;
                    ffs[e][r] = gelu_exact(part[e*2048 + r] + part[e*2048 + 1024 + r] + bf[r]);
                }
            }
            __syncthreads();

            // ---- FF2 + residual + LN2 ----
            gemv2<DM, FFD>(&g_wff2T[l][0][0], ffs[0], ffs[1], part, t);
            __syncthreads();
            {
                const float* p = part + e8*2048 + r8;
                float v = xs[e8][r8] + b_ff2[l*DM + r8]
                        + p[0]+p[256]+p[512]+p[768]+p[1024]+p[1280]+p[1536]+p[1792];
                float s1 = v, s2 = v*v;
                block_reduce2_dual(s1, s2, red, lane, warp);
                float m   = s1 * (1.f/256.f);
                float var = s2 * (1.f/256.f) - m*m;
                xs[e8][r8] = (v - m) * rsqrtf(var + 1e-5f) * ln2_g[l*DM + r8] + ln2_b[l*DM + r8];
            }
            __syncthreads();
        }

        // ---- head: p1 (gelu) then p2 (scalar) ----
        gemv2<128, DM>(&g_wp1T[0][0], xs[0], xs[1], part, t);
        __syncthreads();
        if (t < 256) {
            int e = t >> 7, r = t & 127;
            float acc = b_p1[r];
            #pragma unroll
            for (int s = 0; s < 16; ++s) acc += part[e*2048 + s*128 + r];
            h1[e][r] = gelu_exact(acc);
        }
        __syncthreads();
        if (warp < 2) {
            float v = w_p2[lane]      * h1[warp][lane]
                    + w_p2[lane + 32] * h1[warp][lane + 32]
                    + w_p2[lane + 64] * h1[warp][lane + 64]
                    + w_p2[lane + 96] * h1[warp][lane + 96];
            #pragma unroll
            for (int m = 16; m; m >>= 1) v += __shfl_xor_sync(0xffffffffu, v, m);
            if (lane == 0) {
                float d = v + b_p2[0];
                out[(b0 + warp)*NSEQ + k] = d;
                sdelta[warp] = d;
            }
        }
        __syncthreads();
    }
}

extern "C" void kernel_launch(void* const* d_in, const int* in_sizes, int n_in,
                              void* d_out, int out_size)
{
    const float* feat  = (const float*)d_in[0];
    const float* w_in  = (const float*)d_in[1];
    const float* b_in  = (const float*)d_in[2];
    const float* w_qkv = (const float*)d_in[3];
    const float* b_qkv = (const float*)d_in[4];
    const float* w_o   = (const float*)d_in[5];
    const float* b_o   = (const float*)d_in[6];
    const float* ln1_g = (const float*)d_in[7];
    const float* ln1_b = (const float*)d_in[8];
    const float* w_ff1 = (const float*)d_in[9];
    const float* b_ff1 = (const float*)d_in[10];
    const float* w_ff2 = (const float*)d_in[11];
    const float* b_ff2 = (const float*)d_in[12];
    const float* ln2_g = (const float*)d_in[13];
    const float* ln2_b = (const float*)d_in[14];
    const float* w_p1  = (const float*)d_in[15];
    const float* b_p1  = (const float*)d_in[16];
    const float* w_p2  = (const float*)d_in[17];
    const float* b_p2  = (const float*)d_in[18];
    float* out = (float*)d_out;

    prep_kernel<<<512, 256>>>(w_qkv, w_o, w_ff1, w_ff2, w_in, w_p1);
    hedge_kernel<<<NB/2, NTH>>>(feat, b_in, b_qkv, b_o, ln1_g, ln1_b,
                                b_ff1, b_ff2, ln2_g, ln2_b, b_p1, w_p2, b_p2, out);
}

// round 5
// speedup vs baseline: 1.5567x; 1.5567x over previous
#include <cuda_runtime.h>
#include <cooperative_groups.h>
#include <math.h>

namespace cg = cooperative_groups;

#define NL   3
#define NB   64
#define NSEQ 48
#define DM   256
#define NH   8
#define HDM  32
#define FFD  1024
#define INP  17
#define NTH  512
#define RH   128   // row-half of DM-output GEMVs per CTA
#define FH   512   // row-half of FF1 output per CTA

// ---------------- static device scratch ----------------
__device__ float g_wqT[NL][2][DM][RH];    // [l][rank][j][rr]: Q rows rank*128+rr
__device__ float g_wkT[NL][2][DM][RH];
__device__ float g_wvT[NL][2][DM][RH];
__device__ float g_woT[NL][2][DM][RH];
__device__ float g_wff1T[NL][2][DM][FH];  // FF1 rows rank*512+rr
__device__ float g_wff2T[NL][2][FFD][RH]; // FF2 rows rank*128+rr
__device__ float g_winT[INP][DM];
__device__ float g_wp1T[DM][128];
__device__ float g_kc[NL][NB][NSEQ][DM];
__device__ float g_vc[NL][NB][NSEQ][DM];

// ---------------- prep: transpose + split weights ----------------
__global__ void prep_kernel(const float* __restrict__ w_qkv, const float* __restrict__ w_o,
                            const float* __restrict__ w_ff1, const float* __restrict__ w_ff2,
                            const float* __restrict__ w_in,  const float* __restrict__ w_p1)
{
    int tid = blockIdx.x * blockDim.x + threadIdx.x;
    int nth = gridDim.x * blockDim.x;

    for (int i = tid; i < NL*3*DM*DM; i += nth) {
        int l = i / (3*DM*DM); int rem = i - l*3*DM*DM; int row = rem / DM; int j = rem - row*DM;
        float v = w_qkv[i];
        int sel = row >> 8; int rr = row & 255;
        int r = rr >> 7; int rh = rr & 127;
        if (sel == 0)      g_wqT[l][r][j][rh] = v;
        else if (sel == 1) g_wkT[l][r][j][rh] = v;
        else               g_wvT[l][r][j][rh] = v;
    }
    for (int i = tid; i < NL*DM*DM; i += nth) {
        int l = i / (DM*DM); int rem = i - l*DM*DM; int row = rem / DM; int j = rem - row*DM;
        g_woT[l][row >> 7][j][row & 127] = w_o[i];
    }
    for (int i = tid; i < NL*FFD*DM; i += nth) {
        int l = i / (FFD*DM); int rem = i - l*FFD*DM; int row = rem / DM; int j = rem - row*DM;
        g_wff1T[l][row >> 9][j][row & 511] = w_ff1[i];
    }
    for (int i = tid; i < NL*DM*FFD; i += nth) {
        int l = i / (DM*FFD); int rem = i - l*DM*FFD; int row = rem / FFD; int j = rem - row*FFD;
        g_wff2T[l][row >> 7][j][row & 127] = w_ff2[i];
    }
    for (int i = tid; i < DM*INP; i += nth) {
        int r = i / INP; int j = i - r*INP;
        g_winT[j][r] = w_in[i];
    }
    for (int i = tid; i < 128*DM; i += nth) {
        int r = i / DM; int j = i - r*DM;
        g_wp1T[j][r] = w_p1[i];
    }
}

// ---------------- GEMV (single RHS): thread owns 4 consecutive rows, j split ----
template<int O, int I>
__device__ __forceinline__ void gemv1(const float* __restrict__ wT,
                                      const float* __restrict__ x,
                                      float* __restrict__ part, int t)
{
    constexpr int G  = O / 4;
    constexpr int S  = NTH / G;
    constexpr int JC = I / S;
    const int g = t % G;
    const int s = t / G;
    const float4* __restrict__ w4 = reinterpret_cast<const float4*>(wT);
    const float4* __restrict__ x4 = reinterpret_cast<const float4*>(x);
    float ax=0.f, ay=0.f, az=0.f, aw=0.f;
    const int jb = s * JC;
    #pragma unroll 4
    for (int u = 0; u < JC/4; ++u) {
        float4 xv = x4[(jb >> 2) + u];
        const float4* wp = w4 + (size_t)(jb + 4*u) * G + g;
        float4 w0 = wp[0];
        float4 w1 = wp[G];
        float4 w2 = wp[2*G];
        float4 w3 = wp[3*G];
        ax=fmaf(w0.x,xv.x,ax); ay=fmaf(w0.y,xv.x,ay); az=fmaf(w0.z,xv.x,az); aw=fmaf(w0.w,xv.x,aw);
        ax=fmaf(w1.x,xv.y,ax); ay=fmaf(w1.y,xv.y,ay); az=fmaf(w1.z,xv.y,az); aw=fmaf(w1.w,xv.y,aw);
        ax=fmaf(w2.x,xv.z,ax); ay=fmaf(w2.y,xv.z,ay); az=fmaf(w2.z,xv.z,az); aw=fmaf(w2.w,xv.z,aw);
        ax=fmaf(w3.x,xv.w,ax); ay=fmaf(w3.y,xv.w,ay); az=fmaf(w3.z,xv.w,az); aw=fmaf(w3.w,xv.w,aw);
    }
    float4 rv; rv.x=ax; rv.y=ay; rv.z=az; rv.w=aw;
    reinterpret_cast<float4*>(part)[s*G + g] = rv;
}

__device__ __forceinline__ float gelu_exact(float x) {
    return 0.5f * x * (1.0f + erff(x * 0.70710678118654746f));
}

// reduce two scalars over the block (512 threads, 16 warps; inactive lanes pass 0)
__device__ __forceinline__ void block_reduce2(float& a, float& b, float* red, int lane, int warp)
{
    #pragma unroll
    for (int m = 16; m; m >>= 1) {
        a += __shfl_xor_sync(0xffffffffu, a, m);
        b += __shfl_xor_sync(0xffffffffu, b, m);
    }
    if (lane == 0) { red[warp] = a; red[16 + warp] = b; }
    __syncthreads();
    if (warp == 0) {
        float aa = (lane < 16) ? red[lane]      : 0.f;
        float bb = (lane < 16) ? red[16 + lane] : 0.f;
        #pragma unroll
        for (int m = 8; m; m >>= 1) {
            aa += __shfl_xor_sync(0xffffffffu, aa, m);
            bb += __shfl_xor_sync(0xffffffffu, bb, m);
        }
        if (lane == 0) { red[32] = aa; red[33] = bb; }
    }
    __syncthreads();
    a = red[32]; b = red[33];
}

// ---------------- main: 2-CTA cluster per batch element ----------------
__global__ __launch_bounds__(NTH, 1) __cluster_dims__(2, 1, 1)
void hedge_kernel(
    const float* __restrict__ feat,
    const float* __restrict__ b_in,
    const float* __restrict__ b_qkv,
    const float* __restrict__ b_o,
    const float* __restrict__ ln1_g, const float* __restrict__ ln1_b,
    const float* __restrict__ b_ff1, const float* __restrict__ b_ff2,
    const float* __restrict__ ln2_g, const float* __restrict__ ln2_b,
    const float* __restrict__ b_p1,
    const float* __restrict__ w_p2,  const float* __restrict__ b_p2,
    float* __restrict__ out)
{
    cg::cluster_group cl = cg::this_cluster();

    const int b    = blockIdx.x >> 1;   // batch element
    const int r    = blockIdx.x & 1;    // cluster rank
    const int peer = r ^ 1;
    const int t    = threadIdx.x;
    const int lane = t & 31;
    const int warp = t >> 5;

    __shared__ __align__(16) float xs[DM];       // full x (identical in both CTAs)
    __shared__ __align__(16) float vfull[DM];    // pre-LN exchange buffer
    __shared__ __align__(16) float qs[RH];       // own q half
    __shared__ __align__(16) float ctx[DM];      // full ctx after exchange
    __shared__ __align__(16) float ctxp[4][RH];  // attention sub-partials
    __shared__ __align__(16) float ffs[FFD];     // full ff after exchange
    __shared__ __align__(16) float part[2048];
    __shared__ float sc[4][NSEQ];
    __shared__ float h1[128];
    __shared__ float xin[INP + 3];
    __shared__ float red[40];
    __shared__ float sdelta;

    float* ctx_pr   = cl.map_shared_rank(ctx,   peer);
    float* vfull_pr = cl.map_shared_rank(vfull, peer);
    float* ffs_pr   = cl.map_shared_rank(ffs,   peer);

    const float div_t = expf((float)(t & ~1) * (-9.210340371976184f / 256.f));
    const float scale = 0.17677669529663687f;  // 1/sqrt(32)

    if (t == 0) { sdelta = 0.f; xin[16] = 0.f; }
    __syncthreads();

    for (int k = 0; k < NSEQ; ++k) {
        // ---- token input (redundant in both CTAs) ----
        if (t < 16) xin[t] = feat[((b*NSEQ) + k)*16 + t];
        __syncthreads();

        // ---- input projection + PE (redundant, full 256 rows) ----
        if (t < 256) {
            float acc = b_in[t];
            #pragma unroll
            for (int j = 0; j < INP; ++j) acc = fmaf(g_winT[j][t], xin[j], acc);
            float ang = (float)k * div_t;
            acc += (t & 1) ? cosf(ang) : sinf(ang);
            xs[t] = acc;
        }
        __syncthreads();

        for (int l = 0; l < NL; ++l) {
            const float* bq = b_qkv + l*3*DM;

            // ---- Q half ----
            gemv1<RH, DM>(&g_wqT[l][r][0][0], xs, part, t);
            __syncthreads();
            if (t < RH) {
                float a = bq[r*RH + t];
                #pragma unroll
                for (int s = 0; s < 16; ++s) a += part[s*RH + t];
                qs[t] = a;
            }
            __syncthreads();
            // ---- K half -> cache ----
            gemv1<RH, DM>(&g_wkT[l][r][0][0], xs, part, t);
            __syncthreads();
            if (t < RH) {
                float a = bq[DM + r*RH + t];
                #pragma unroll
                for (int s = 0; s < 16; ++s) a += part[s*RH + t];
                g_kc[l][b][k][r*RH + t] = a;
            }
            __syncthreads();
            // ---- V half -> cache ----
            gemv1<RH, DM>(&g_wvT[l][r][0][0], xs, part, t);
            __syncthreads();
            if (t < RH) {
                float a = bq[2*DM + r*RH + t];
                #pragma unroll
                for (int s = 0; s < 16; ++s) a += part[s*RH + t];
                g_vc[l][b][k][r*RH + t] = a;
            }
            __syncthreads();

            // ---- attention: 4 local heads, 4 warps per head (sub = position stride) ----
            {
                const int h   = warp >> 2;        // local head 0..3
                const int sub = warp & 3;
                const int offl = h*HDM + lane;    // index into own q half
                const int dimg = r*RH + offl;     // dim in full cache row
                const float ql = qs[offl];
                const float* kcp = &g_kc[l][b][0][0];
                const float* vcp = &g_vc[l][b][0][0];
                for (int p = sub; p <= k; p += 4) {
                    float s0 = ql * kcp[p*DM + dimg];
                    #pragma unroll
                    for (int m = 16; m; m >>= 1) s0 += __shfl_xor_sync(0xffffffffu, s0, m);
                    if (lane == 0) sc[h][p] = s0 * scale;
                }
                __syncthreads();
                if (sub == 0) {  // one warp per head runs softmax
                    float v0 = (lane      <= k) ? sc[h][lane]      : -3.0e38f;
                    float v1 = (lane + 32 <= k) ? sc[h][lane + 32] : -3.0e38f;
                    float mx = fmaxf(v0, v1);
                    #pragma unroll
                    for (int m = 16; m; m >>= 1) mx = fmaxf(mx, __shfl_xor_sync(0xffffffffu, mx, m));
                    float e0 = (lane      <= k) ? expf(v0 - mx) : 0.f;
                    float e1 = (lane + 32 <= k) ? expf(v1 - mx) : 0.f;
                    float sum = e0 + e1;
                    #pragma unroll
                    for (int m = 16; m; m >>= 1) sum += __shfl_xor_sync(0xffffffffu, sum, m);
                    float inv = 1.f / sum;
                    if (lane      <= k) sc[h][lane]      = e0 * inv;
                    if (lane + 32 <= k) sc[h][lane + 32] = e1 * inv;
                }
                __syncthreads();
                float acc = 0.f;
                for (int p = sub; p <= k; p += 4)
                    acc = fmaf(sc[h][p], vcp[p*DM + dimg], acc);
                ctxp[sub][offl] = acc;
            }
            __syncthreads();
            if (t < RH) {
                float c = ctxp[0][t] + ctxp[1][t] + ctxp[2][t] + ctxp[3][t];
                ctx[r*RH + t]    = c;
                ctx_pr[r*RH + t] = c;     // DSMEM: give peer our ctx half
            }
            cl.sync();                     // ctx complete in both CTAs

            // ---- O projection half + residual -> exchange pre-LN1 ----
            gemv1<RH, DM>(&g_woT[l][r][0][0], ctx, part, t);
            __syncthreads();
            if (t < RH) {
                float a = xs[r*RH + t] + b_o[l*DM + r*RH + t];
                #pragma unroll
                for (int s = 0; s < 16; ++s) a += part[s*RH + t];
                vfull[r*RH + t]    = a;
                vfull_pr[r*RH + t] = a;
            }
            cl.sync();                     // vfull complete

            // ---- LN1 (redundant, full row) ----
            {
                float v = (t < 256) ? vfull[t] : 0.f;
                float s1 = v, s2 = v*v;
                block_reduce2(s1, s2, red, lane, warp);
                if (t < 256) {
                    float m   = s1 * (1.f/256.f);
                    float var = s2 * (1.f/256.f) - m*m;
                    xs[t] = (v - m) * rsqrtf(var + 1e-5f) * ln1_g[l*DM + t] + ln1_b[l*DM + t];
                }
            }
            __syncthreads();

            // ---- FF1 half + GELU -> exchange ff ----
            gemv1<FH, DM>(&g_wff1T[l][r][0][0], xs, part, t);
            __syncthreads();
            {
                float a = b_ff1[l*FFD + r*FH + t];
                #pragma unroll
                for (int s = 0; s < 4; ++s) a += part[s*FH + t];
                float gv = gelu_exact(a);
                ffs[r*FH + t]    = gv;
                ffs_pr[r*FH + t] = gv;
            }
            cl.sync();                     // ffs complete

            // ---- FF2 half + residual -> exchange pre-LN2 ----
            gemv1<RH, FFD>(&g_wff2T[l][r][0][0], ffs, part, t);
            __syncthreads();
            if (t < RH) {
                float a = xs[r*RH + t] + b_ff2[l*DM + r*RH + t];
                #pragma unroll
                for (int s = 0; s < 16; ++s) a += part[s*RH + t];
                vfull[r*RH + t]    = a;
                vfull_pr[r*RH + t] = a;
            }
            cl.sync();                     // vfull complete

            // ---- LN2 (redundant, full row) ----
            {
                float v = (t < 256) ? vfull[t] : 0.f;
                float s1 = v, s2 = v*v;
                block_reduce2(s1, s2, red, lane, warp);
                if (t < 256) {
                    float m   = s1 * (1.f/256.f);
                    float var = s2 * (1.f/256.f) - m*m;
                    xs[t] = (v - m) * rsqrtf(var + 1e-5f) * ln2_g[l*DM + t] + ln2_b[l*DM + t];
                }
            }
            __syncthreads();
        }

        // ---- head (redundant in both CTAs; no cluster syncs) ----
        gemv1<128, DM>(&g_wp1T[0][0], xs, part, t);
        __syncthreads();
        if (t < 128) {
            float a = b_p1[t];
            #pragma unroll
            for (int s = 0; s < 16; ++s) a += part[s*128 + t];
            h1[t] = gelu_exact(a);
        }
        __syncthreads();
        if (warp == 0) {
            float v = w_p2[lane]      * h1[lane]
                    + w_p2[lane + 32] * h1[lane + 32]
                    + w_p2[lane + 64] * h1[lane + 64]
                    + w_p2[lane + 96] * h1[lane + 96];
            #pragma unroll
            for (int m = 16; m; m >>= 1) v += __shfl_xor_sync(0xffffffffu, v, m);
            if (lane == 0) {
                float d = v + b_p2[0];
                if (r == 0) out[b*NSEQ + k] = d;
                sdelta  = d;
                xin[16] = d;
            }
        }
        __syncthreads();
    }
    cl.sync();   // no CTA exits while peer DSMEM traffic could be in flight
}

extern "C" void kernel_launch(void* const* d_in, const int* in_sizes, int n_in,
                              void* d_out, int out_size)
{
    const float* feat  = (const float*)d_in[0];
    const float* w_in  = (const float*)d_in[1];
    const float* b_in  = (const float*)d_in[2];
    const float* w_qkv = (const float*)d_in[3];
    const float* b_qkv = (const float*)d_in[4];
    const float* w_o   = (const float*)d_in[5];
    const float* b_o   = (const float*)d_in[6];
    const float* ln1_g = (const float*)d_in[7];
    const float* ln1_b = (const float*)d_in[8];
    const float* w_ff1 = (const float*)d_in[9];
    const float* b_ff1 = (const float*)d_in[10];
    const float* w_ff2 = (const float*)d_in[11];
    const float* b_ff2 = (const float*)d_in[12];
    const float* ln2_g = (const float*)d_in[13];
    const float* ln2_b = (const float*)d_in[14];
    const float* w_p1  = (const float*)d_in[15];
    const float* b_p1  = (const float*)d_in[16];
    const float* w_p2  = (const float*)d_in[17];
    const float* b_p2  = (const float*)d_in[18];
    float* out = (float*)d_out;

    prep_kernel<<<512, 256>>>(w_qkv, w_o, w_ff1, w_ff2, w_in, w_p1);
    hedge_kernel<<<NB*2, NTH>>>(feat, b_in, b_qkv, b_o, ln1_g, ln1_b,
                                b_ff1, b_ff2, ln2_g, ln2_b, b_p1, w_p2, b_p2, out);
}

// round 6
// speedup vs baseline: 1.7996x; 1.1560x over previous
#include <cuda_runtime.h>
#include <cooperative_groups.h>
#include <math.h>

namespace cg = cooperative_groups;

#define NL   3
#define NB   64
#define NSEQ 48
#define DM   256
#define HDM  32
#define FFD  1024
#define INP  17
#define NTH  512
#define CSZ  4     // CTAs per cluster
#define RQ   64    // DM-output rows per CTA
#define RF   256   // FF1 rows per CTA

// ---------------- static device scratch ----------------
__device__ float g_wqT[NL][CSZ][DM][RQ];    // [l][rank][j][rh] : Q rows rank*64+rh
__device__ float g_wkT[NL][CSZ][DM][RQ];
__device__ float g_wvT[NL][CSZ][DM][RQ];
__device__ float g_woT[NL][CSZ][DM][RQ];
__device__ float g_wff1T[NL][CSZ][DM][RF];  // FF1 rows rank*256+rh
__device__ float g_wff2T[NL][CSZ][FFD][RQ]; // FF2 rows rank*64+rh
__device__ float g_winT[INP][DM];
__device__ float g_wp1T[DM][128];
__device__ float g_kc[NL][NB][NSEQ][DM];
__device__ float g_vc[NL][NB][NSEQ][DM];

// ---------------- prep: transpose + split weights ----------------
__global__ void prep_kernel(const float* __restrict__ w_qkv, const float* __restrict__ w_o,
                            const float* __restrict__ w_ff1, const float* __restrict__ w_ff2,
                            const float* __restrict__ w_in,  const float* __restrict__ w_p1)
{
    int tid = blockIdx.x * blockDim.x + threadIdx.x;
    int nth = gridDim.x * blockDim.x;

    for (int i = tid; i < NL*3*DM*DM; i += nth) {
        int l = i / (3*DM*DM); int rem = i - l*3*DM*DM; int row = rem / DM; int j = rem - row*DM;
        float v = w_qkv[i];
        int sel = row >> 8; int rr = row & 255;
        int r = rr >> 6; int rh = rr & 63;
        if (sel == 0)      g_wqT[l][r][j][rh] = v;
        else if (sel == 1) g_wkT[l][r][j][rh] = v;
        else               g_wvT[l][r][j][rh] = v;
    }
    for (int i = tid; i < NL*DM*DM; i += nth) {
        int l = i / (DM*DM); int rem = i - l*DM*DM; int row = rem / DM; int j = rem - row*DM;
        g_woT[l][row >> 6][j][row & 63] = w_o[i];
    }
    for (int i = tid; i < NL*FFD*DM; i += nth) {
        int l = i / (FFD*DM); int rem = i - l*FFD*DM; int row = rem / DM; int j = rem - row*DM;
        g_wff1T[l][row >> 8][j][row & 255] = w_ff1[i];
    }
    for (int i = tid; i < NL*DM*FFD; i += nth) {
        int l = i / (DM*FFD); int rem = i - l*DM*FFD; int row = rem / FFD; int j = rem - row*FFD;
        g_wff2T[l][row >> 6][j][row & 63] = w_ff2[i];
    }
    for (int i = tid; i < DM*INP; i += nth) {
        int r = i / INP; int j = i - r*INP;
        g_winT[j][r] = w_in[i];
    }
    for (int i = tid; i < 128*DM; i += nth) {
        int r = i / DM; int j = i - r*DM;
        g_wp1T[j][r] = w_p1[i];
    }
}

// ---------------- dual-RHS GEMV: each weight float4 feeds both elements.
// part layout: elem0 [0,2048), elem1 [2048,4096). S*O == 2048 always. ----
template<int O, int I>
__device__ __forceinline__ void gemv2(const float* __restrict__ wT,
                                      const float* __restrict__ x0,
                                      const float* __restrict__ x1,
                                      float* __restrict__ part, int t)
{
    constexpr int G  = O / 4;
    constexpr int S  = NTH / G;
    constexpr int JC = I / S;
    const int g = t % G;
    const int s = t / G;
    const float4* __restrict__ w4  = reinterpret_cast<const float4*>(wT);
    const float4* __restrict__ xa4 = reinterpret_cast<const float4*>(x0);
    const float4* __restrict__ xb4 = reinterpret_cast<const float4*>(x1);
    float ax=0.f, ay=0.f, az=0.f, aw=0.f;
    float bx=0.f, by=0.f, bz=0.f, bw=0.f;
    const int jb = s * JC;
    #pragma unroll 2
    for (int u = 0; u < JC/4; ++u) {
        float4 av = xa4[(jb >> 2) + u];
        float4 bv = xb4[(jb >> 2) + u];
        const float4* wp = w4 + (size_t)(jb + 4*u) * G + g;
        float4 w0 = wp[0];
        float4 w1 = wp[G];
        float4 w2 = wp[2*G];
        float4 w3 = wp[3*G];
        ax=fmaf(w0.x,av.x,ax); ay=fmaf(w0.y,av.x,ay); az=fmaf(w0.z,av.x,az); aw=fmaf(w0.w,av.x,aw);
        bx=fmaf(w0.x,bv.x,bx); by=fmaf(w0.y,bv.x,by); bz=fmaf(w0.z,bv.x,bz); bw=fmaf(w0.w,bv.x,bw);
        ax=fmaf(w1.x,av.y,ax); ay=fmaf(w1.y,av.y,ay); az=fmaf(w1.z,av.y,az); aw=fmaf(w1.w,av.y,aw);
        bx=fmaf(w1.x,bv.y,bx); by=fmaf(w1.y,bv.y,by); bz=fmaf(w1.z,bv.y,bz); bw=fmaf(w1.w,bv.y,bw);
        ax=fmaf(w2.x,av.z,ax); ay=fmaf(w2.y,av.z,ay); az=fmaf(w2.z,av.z,az); aw=fmaf(w2.w,av.z,aw);
        bx=fmaf(w2.x,bv.z,bx); by=fmaf(w2.y,bv.z,by); bz=fmaf(w2.z,bv.z,bz); bw=fmaf(w2.w,bv.z,bw);
        ax=fmaf(w3.x,av.w,ax); ay=fmaf(w3.y,av.w,ay); az=fmaf(w3.z,av.w,az); aw=fmaf(w3.w,av.w,aw);
        bx=fmaf(w3.x,bv.w,bx); by=fmaf(w3.y,bv.w,by); bz=fmaf(w3.z,bv.w,bz); bw=fmaf(w3.w,bv.w,bw);
    }
    float4 A; A.x=ax; A.y=ay; A.z=az; A.w=aw;
    float4 B; B.x=bx; B.y=by; B.z=bz; B.w=bw;
    reinterpret_cast<float4*>(part)[s*G + g]       = A;
    reinterpret_cast<float4*>(part)[512 + s*G + g] = B;
}

__device__ __forceinline__ float gelu_exact(float x) {
    return 0.5f * x * (1.0f + erff(x * 0.70710678118654746f));
}

// dual-element block reduction: warps 0-7 hold element-0 values, 8-15 element-1.
__device__ __forceinline__ void block_reduce2_dual(float& a, float& b, float* red, int lane, int warp)
{
    #pragma unroll
    for (int m = 16; m; m >>= 1) {
        a += __shfl_xor_sync(0xffffffffu, a, m);
        b += __shfl_xor_sync(0xffffffffu, b, m);
    }
    if (lane == 0) { red[warp] = a; red[32 + warp] = b; }
    __syncthreads();
    if (warp < 2) {
        float aa = (lane < 8) ? red[warp*8 + lane]      : 0.f;
        float bb = (lane < 8) ? red[32 + warp*8 + lane] : 0.f;
        #pragma unroll
        for (int m = 4; m; m >>= 1) {
            aa += __shfl_xor_sync(0xffffffffu, aa, m);
            bb += __shfl_xor_sync(0xffffffffu, bb, m);
        }
        if (lane == 0) { red[48 + warp] = aa; red[52 + warp] = bb; }
    }
    __syncthreads();
    int e = warp >> 3;
    a = red[48 + e];
    b = red[52 + e];
}

// ---------------- main: 4-CTA cluster per 2 batch elements ----------------
__global__ __launch_bounds__(NTH, 1) __cluster_dims__(CSZ, 1, 1)
void hedge_kernel(
    const float* __restrict__ feat,
    const float* __restrict__ b_in,
    const float* __restrict__ b_qkv,
    const float* __restrict__ b_o,
    const float* __restrict__ ln1_g, const float* __restrict__ ln1_b,
    const float* __restrict__ b_ff1, const float* __restrict__ b_ff2,
    const float* __restrict__ ln2_g, const float* __restrict__ ln2_b,
    const float* __restrict__ b_p1,
    const float* __restrict__ w_p2,  const float* __restrict__ b_p2,
    float* __restrict__ out)
{
    cg::cluster_group cl = cg::this_cluster();

    const int cid  = blockIdx.x >> 2;    // cluster id -> elements 2*cid, 2*cid+1
    const int r    = blockIdx.x & 3;     // cluster rank
    const int b0   = cid * 2;
    const int t    = threadIdx.x;
    const int lane = t & 31;
    const int warp = t >> 5;

    __shared__ __align__(16) float xs[2][DM];       // full x (identical in all CTAs)
    __shared__ __align__(16) float vfull[2][DM];    // pre-LN exchange buffer
    __shared__ __align__(16) float qs[2][RQ];       // own q slice
    __shared__ __align__(16) float ctx[2][DM];      // full ctx after exchange
    __shared__ __align__(16) float ctxp[4][2][RQ];  // attention sub-partials
    __shared__ __align__(16) float ffs[2][FFD];     // full ff after exchange
    __shared__ __align__(16) float part[4096];
    __shared__ float sc[2][2][NSEQ];
    __shared__ float h1[2][128];
    __shared__ float xin[2][20];
    __shared__ float red[64];
    __shared__ float sdelta[2];

    const float div_t = expf((float)(t & 254) * (-9.210340371976184f / 256.f));
    const float scale = 0.17677669529663687f;  // 1/sqrt(32)

    if (t < 2) { sdelta[t] = 0.f; xin[t][16] = 0.f; }
    __syncthreads();

    for (int k = 0; k < NSEQ; ++k) {
        // ---- token inputs (redundant in all CTAs) ----
        if (t < 32) {
            int e = t >> 4, j = t & 15;
            xin[e][j] = feat[((b0 + e)*NSEQ + k)*16 + j];
        }
        __syncthreads();

        // ---- input projection + PE (redundant, both elements) ----
        {
            int e = t >> 8, rr = t & 255;
            float acc = b_in[rr];
            #pragma unroll
            for (int j = 0; j < INP; ++j) acc = fmaf(g_winT[j][rr], xin[e][j], acc);
            float ang = (float)k * div_t;            // div_t derived from (t&254): ok since rr==t&255 parity-paired
            acc += (rr & 1) ? cosf(ang) : sinf(ang);
            xs[e][rr] = acc;
        }
        __syncthreads();

        for (int l = 0; l < NL; ++l) {
            const float* bq = b_qkv + l*3*DM;

            // ---- Q slice ----
            gemv2<RQ, DM>(&g_wqT[l][r][0][0], xs[0], xs[1], part, t);
            __syncthreads();
            if (t < 128) {
                int e = t >> 6, rr = t & 63;
                float a = bq[r*RQ + rr];
                const float* p = part + e*2048 + rr;
                #pragma unroll
                for (int s = 0; s < 32; ++s) a += p[s*RQ];
                qs[e][rr] = a;
            }
            __syncthreads();
            // ---- K slice -> cache ----
            gemv2<RQ, DM>(&g_wkT[l][r][0][0], xs[0], xs[1], part, t);
            __syncthreads();
            if (t < 128) {
                int e = t >> 6, rr = t & 63;
                float a = bq[DM + r*RQ + rr];
                const float* p = part + e*2048 + rr;
                #pragma unroll
                for (int s = 0; s < 32; ++s) a += p[s*RQ];
                g_kc[l][b0+e][k][r*RQ + rr] = a;
            }
            __syncthreads();
            // ---- V slice -> cache ----
            gemv2<RQ, DM>(&g_wvT[l][r][0][0], xs[0], xs[1], part, t);
            __syncthreads();
            if (t < 128) {
                int e = t >> 6, rr = t & 63;
                float a = bq[2*DM + r*RQ + rr];
                const float* p = part + e*2048 + rr;
                #pragma unroll
                for (int s = 0; s < 32; ++s) a += p[s*RQ];
                g_vc[l][b0+e][k][r*RQ + rr] = a;
            }
            __syncthreads();

            // ---- attention: 2 local heads x 2 elements, 4 sub-warps each ----
            {
                const int e    = warp >> 3;          // element
                const int hl   = (warp >> 2) & 1;    // local head
                const int sub  = warp & 3;
                const int offl = hl*HDM + lane;      // idx in own 64-dim slice
                const int dimg = r*RQ + offl;        // dim in full row
                const float ql = qs[e][offl];
                const float* kcp = &g_kc[l][b0+e][0][0];
                const float* vcp = &g_vc[l][b0+e][0][0];
                for (int p = sub; p <= k; p += 4) {
                    float s0 = ql * kcp[p*DM + dimg];
                    #pragma unroll
                    for (int m = 16; m; m >>= 1) s0 += __shfl_xor_sync(0xffffffffu, s0, m);
                    if (lane == 0) sc[e][hl][p] = s0 * scale;
                }
                __syncthreads();
                if (sub == 0) {   // warps 0,4,8,12 run softmax for (e,hl)
                    float v0 = (lane      <= k) ? sc[e][hl][lane]      : -3.0e38f;
                    float v1 = (lane + 32 <= k) ? sc[e][hl][lane + 32] : -3.0e38f;
                    float mx = fmaxf(v0, v1);
                    #pragma unroll
                    for (int m = 16; m; m >>= 1) mx = fmaxf(mx, __shfl_xor_sync(0xffffffffu, mx, m));
                    float e0 = (lane      <= k) ? expf(v0 - mx) : 0.f;
                    float e1 = (lane + 32 <= k) ? expf(v1 - mx) : 0.f;
                    float sum = e0 + e1;
                    #pragma unroll
                    for (int m = 16; m; m >>= 1) sum += __shfl_xor_sync(0xffffffffu, sum, m);
                    float inv = 1.f / sum;
                    if (lane      <= k) sc[e][hl][lane]      = e0 * inv;
                    if (lane + 32 <= k) sc[e][hl][lane + 32] = e1 * inv;
                }
                __syncthreads();
                float acc = 0.f;
                for (int p = sub; p <= k; p += 4)
                    acc = fmaf(sc[e][hl][p], vcp[p*DM + dimg], acc);
                ctxp[sub][e][offl] = acc;
            }
            __syncthreads();
            // combine sub-partials + broadcast ctx slice to all ranks
            if (t < 128) {
                int e = t >> 6, rr = t & 63;
                float c = ctxp[0][e][rr] + ctxp[1][e][rr] + ctxp[2][e][rr] + ctxp[3][e][rr];
                #pragma unroll
                for (int pr = 0; pr < CSZ; ++pr)
                    cl.map_shared_rank(&ctx[0][0], pr)[e*DM + r*RQ + rr] = c;
            }
            cl.sync();

            // ---- O projection slice + residual -> exchange pre-LN1 ----
            gemv2<RQ, DM>(&g_woT[l][r][0][0], ctx[0], ctx[1], part, t);
            __syncthreads();
            if (t < 128) {
                int e = t >> 6, rr = t & 63;
                float a = xs[e][r*RQ + rr] + b_o[l*DM + r*RQ + rr];
                const float* p = part + e*2048 + rr;
                #pragma unroll
                for (int s = 0; s < 32; ++s) a += p[s*RQ];
                #pragma unroll
                for (int pr = 0; pr < CSZ; ++pr)
                    cl.map_shared_rank(&vfull[0][0], pr)[e*DM + r*RQ + rr] = a;
            }
            cl.sync();

            // ---- LN1 (redundant, both elements) ----
            {
                int e = t >> 8, rr = t & 255;
                float v = vfull[e][rr];
                float s1 = v, s2 = v*v;
                block_reduce2_dual(s1, s2, red, lane, warp);
                float m   = s1 * (1.f/256.f);
                float var = s2 * (1.f/256.f) - m*m;
                xs[e][rr] = (v - m) * rsqrtf(var + 1e-5f) * ln1_g[l*DM + rr] + ln1_b[l*DM + rr];
            }
            __syncthreads();

            // ---- FF1 slice + GELU -> exchange ffs ----
            gemv2<RF, DM>(&g_wff1T[l][r][0][0], xs[0], xs[1], part, t);
            __syncthreads();
            {
                int e = t >> 8, rh = t & 255;
                float a = b_ff1[l*FFD + r*RF + rh];
                const float* p = part + e*2048 + rh;
                #pragma unroll
                for (int s = 0; s < 8; ++s) a += p[s*RF];
                float gv = gelu_exact(a);
                #pragma unroll
                for (int pr = 0; pr < CSZ; ++pr)
                    cl.map_shared_rank(&ffs[0][0], pr)[e*FFD + r*RF + rh] = gv;
            }
            cl.sync();

            // ---- FF2 slice + residual -> exchange pre-LN2 ----
            gemv2<RQ, FFD>(&g_wff2T[l][r][0][0], ffs[0], ffs[1], part, t);
            __syncthreads();
            if (t < 128) {
                int e = t >> 6, rr = t & 63;
                float a = xs[e][r*RQ + rr] + b_ff2[l*DM + r*RQ + rr];
                const float* p = part + e*2048 + rr;
                #pragma unroll
                for (int s = 0; s < 32; ++s) a += p[s*RQ];
                #pragma unroll
                for (int pr = 0; pr < CSZ; ++pr)
                    cl.map_shared_rank(&vfull[0][0], pr)[e*DM + r*RQ + rr] = a;
            }
            cl.sync();

            // ---- LN2 (redundant, both elements) ----
            {
                int e = t >> 8, rr = t & 255;
                float v = vfull[e][rr];
                float s1 = v, s2 = v*v;
                block_reduce2_dual(s1, s2, red, lane, warp);
                float m   = s1 * (1.f/256.f);
                float var = s2 * (1.f/256.f) - m*m;
                xs[e][rr] = (v - m) * rsqrtf(var + 1e-5f) * ln2_g[l*DM + rr] + ln2_b[l*DM + rr];
            }
            __syncthreads();
        }

        // ---- head (redundant in all CTAs; no cluster syncs) ----
        gemv2<128, DM>(&g_wp1T[0][0], xs[0], xs[1], part, t);
        __syncthreads();
        if (t < 256) {
            int e = t >> 7, rh = t & 127;
            float a = b_p1[rh];
            const float* p = part + e*2048 + rh;
            #pragma unroll
            for (int s = 0; s < 16; ++s) a += p[s*128];
            h1[e][rh] = gelu_exact(a);
        }
        __syncthreads();
        if (warp < 2) {
            float v = w_p2[lane]      * h1[warp][lane]
                    + w_p2[lane + 32] * h1[warp][lane + 32]
                    + w_p2[lane + 64] * h1[warp][lane + 64]
                    + w_p2[lane + 96] * h1[warp][lane + 96];
            #pragma unroll
            for (int m = 16; m; m >>= 1) v += __shfl_xor_sync(0xffffffffu, v, m);
            if (lane == 0) {
                float d = v + b_p2[0];
                if (r == 0) out[(b0 + warp)*NSEQ + k] = d;
                sdelta[warp]  = d;
                xin[warp][16] = d;
            }
        }
        __syncthreads();
    }
    cl.sync();   // no CTA exits while peer DSMEM traffic could be in flight
}

extern "C" void kernel_launch(void* const* d_in, const int* in_sizes, int n_in,
                              void* d_out, int out_size)
{
    const float* feat  = (const float*)d_in[0];
    const float* w_in  = (const float*)d_in[1];
    const float* b_in  = (const float*)d_in[2];
    const float* w_qkv = (const float*)d_in[3];
    const float* b_qkv = (const float*)d_in[4];
    const float* w_o   = (const float*)d_in[5];
    const float* b_o   = (const float*)d_in[6];
    const float* ln1_g = (const float*)d_in[7];
    const float* ln1_b = (const float*)d_in[8];
    const float* w_ff1 = (const float*)d_in[9];
    const float* b_ff1 = (const float*)d_in[10];
    const float* w_ff2 = (const float*)d_in[11];
    const float* b_ff2 = (const float*)d_in[12];
    const float* ln2_g = (const float*)d_in[13];
    const float* ln2_b = (const float*)d_in[14];
    const float* w_p1  = (const float*)d_in[15];
    const float* b_p1  = (const float*)d_in[16];
    const float* w_p2  = (const float*)d_in[17];
    const float* b_p2  = (const float*)d_in[18];
    float* out = (float*)d_out;

    prep_kernel<<<512, 256>>>(w_qkv, w_o, w_ff1, w_ff2, w_in, w_p1);
    hedge_kernel<<<NB/2*CSZ, NTH>>>(feat, b_in, b_qkv, b_o, ln1_g, ln1_b,
                                    b_ff1, b_ff2, ln2_g, ln2_b, b_p1, w_p2, b_p2, out);
}